// round 6
// baseline (speedup 1.0000x reference)
#include <cuda_runtime.h>
#include <cuda_bf16.h>
#include <cstdint>

// ICPMatcher: exact nearest-neighbor via uniform-grid spatial hashing.
//
// Targets counting-sorted into a 48^3 grid; sources grid-sorted for warp
// coherence. Each source expands Chebyshev rings; ring r pruned iff
// ((r-1)*h)^2 > best_d2 + margin (conservative exact bound). Distance
// compare uses the SAME fma chain + packed (monotone(d')|idx) u64-min as
// the passing brute-force rounds -> identical argmin/tie semantics.
// Scatter atomics only permute in-cell order; u64-min is order-independent
// -> deterministic.
//
// NOTE: no __device__ symbol is ever referenced from host code (that was
// R5's failure); all scratch kernels address the globals directly.

typedef unsigned long long ull;

#define N_MAX   16384
#define G       48
#define NCELLS  (G * G * G)              // 110592 = 108 * 1024
#define NBLK    (NCELLS / 1024)          // 108
#define BBOX    6.0f
#define CELLH   0.25f
#define INVH    4.0f

static __device__ int    g_histT[NCELLS];
static __device__ int    g_histS[NCELLS];
static __device__ int    g_bsumT[NBLK];
static __device__ int    g_bsumS[NBLK];
static __device__ int    g_cellStart[NCELLS + 1];
static __device__ int    g_curT[NCELLS];
static __device__ int    g_curS[NCELLS];
static __device__ float4 g_sortedTgt[N_MAX];   // (x,y,z, bitcast(origIdx))
static __device__ int    g_sortedSrc[N_MAX];

static __device__ __forceinline__ unsigned int map_f32(float f) {
    unsigned int b = __float_as_uint(f);
    return (b & 0x80000000u) ? ~b : (b | 0x80000000u);
}
static __device__ __forceinline__ float unmap_f32(unsigned int m) {
    return __uint_as_float((m & 0x80000000u) ? (m ^ 0x80000000u) : ~m);
}
static __device__ __forceinline__ int clampi(int v, int lo, int hi) {
    return v < lo ? lo : (v > hi ? hi : v);
}
static __device__ __forceinline__ void cellOf(float x, float y, float z,
                                              int& cx, int& cy, int& cz) {
    cx = clampi((int)floorf((x + BBOX) * INVH), 0, G - 1);
    cy = clampi((int)floorf((y + BBOX) * INVH), 0, G - 1);
    cz = clampi((int)floorf((z + BBOX) * INVH), 0, G - 1);
}

// ---- preprocessing (all globals accessed device-side only) -----------------

__global__ void k_zero() {
    int i = blockIdx.x * blockDim.x + threadIdx.x;
    if (i < NCELLS) { g_histT[i] = 0; g_histS[i] = 0; }
}

__global__ void k_count(const float* __restrict__ src,
                        const float* __restrict__ tgt, int n1, int n2) {
    int i = blockIdx.x * blockDim.x + threadIdx.x;
    if (i < n2) {
        int cx, cy, cz;
        cellOf(tgt[3 * i], tgt[3 * i + 1], tgt[3 * i + 2], cx, cy, cz);
        atomicAdd(&g_histT[(cz * G + cy) * G + cx], 1);
    }
    if (i < n1) {
        int cx, cy, cz;
        cellOf(src[3 * i], src[3 * i + 1], src[3 * i + 2], cx, cy, cz);
        atomicAdd(&g_histS[(cz * G + cy) * G + cx], 1);
    }
}

// sel=0 -> target arrays, sel=1 -> source arrays.
__global__ __launch_bounds__(1024) void k_scan1(int sel) {
    __shared__ int sh[1024];
    int* hist = sel ? g_histS : g_histT;
    int* bsum = sel ? g_bsumS : g_bsumT;
    const int t = threadIdx.x;
    const int g = blockIdx.x * 1024 + t;
    const int v = hist[g];
    sh[t] = v;
    __syncthreads();
#pragma unroll
    for (int off = 1; off < 1024; off <<= 1) {
        int add = (t >= off) ? sh[t - off] : 0;
        __syncthreads();
        sh[t] += add;
        __syncthreads();
    }
    hist[g] = sh[t] - v;                     // exclusive within block
    if (t == 1023) bsum[blockIdx.x] = sh[1023];
}

__global__ void k_scan2(int sel) {
    if (threadIdx.x == 0 && blockIdx.x == 0) {
        int* bsum = sel ? g_bsumS : g_bsumT;
        int acc = 0;
        for (int i = 0; i < NBLK; i++) { int v = bsum[i]; bsum[i] = acc; acc += v; }
    }
}

__global__ void k_scan3(int n2) {
    int g = blockIdx.x * blockDim.x + threadIdx.x;
    if (g < NCELLS) {
        int vT = g_histT[g] + g_bsumT[g >> 10];
        g_cellStart[g] = vT;
        g_curT[g] = vT;
        g_curS[g] = g_histS[g] + g_bsumS[g >> 10];
    }
    if (g == 0) g_cellStart[NCELLS] = n2;
}

__global__ void k_scatter(const float* __restrict__ src,
                          const float* __restrict__ tgt, int n1, int n2) {
    int i = blockIdx.x * blockDim.x + threadIdx.x;
    if (i < n2) {
        float x = tgt[3 * i], y = tgt[3 * i + 1], z = tgt[3 * i + 2];
        int cx, cy, cz;
        cellOf(x, y, z, cx, cy, cz);
        int pos = atomicAdd(&g_curT[(cz * G + cy) * G + cx], 1);
        g_sortedTgt[pos] = make_float4(x, y, z, __int_as_float(i));
    }
    if (i < n1) {
        int cx, cy, cz;
        cellOf(src[3 * i], src[3 * i + 1], src[3 * i + 2], cx, cy, cz);
        int pos = atomicAdd(&g_curS[(cz * G + cy) * G + cx], 1);
        g_sortedSrc[pos] = i;
    }
}

// ---- main NN search --------------------------------------------------------

__global__ __launch_bounds__(128) void k_nn(const float* __restrict__ src,
                                            float* __restrict__ out,
                                            int n1, int out_size) {
    const int tid = blockIdx.x * blockDim.x + threadIdx.x;
    if (tid >= n1) return;
    const int i = g_sortedSrc[tid];

    const float x = src[3 * i], y = src[3 * i + 1], z = src[3 * i + 2];
    const float m2x = -2.f * x, m2y = -2.f * y, m2z = -2.f * z;
    const float s2 = fmaf(x, x, fmaf(y, y, z * z));

    int cx, cy, cz;
    cellOf(x, y, z, cx, cy, cz);

    ull best = 0xFFFFFFFFFFFFFFFFull;
    float bestD2 = __int_as_float(0x7f800000);

    for (int r = 0; r <= G; r++) {
        if (r > 0) {
            float lb = (float)(r - 1) * CELLH;
            if (lb * lb > bestD2 + 1e-3f) break;
        }
        const int z0 = max(cz - r, 0), z1 = min(cz + r, G - 1);
        const int y0 = max(cy - r, 0), y1 = min(cy + r, G - 1);
        const int x0 = max(cx - r, 0), x1 = min(cx + r, G - 1);
        for (int zz = z0; zz <= z1; zz++) {
            const int adz = abs(zz - cz);
            for (int yy = y0; yy <= y1; yy++) {
                const int ady = abs(yy - cy);
                const int rowm = max(adz, ady);
                if (rowm < r) {
                    // only xx = cx-r or cx+r are on the shell
#pragma unroll
                    for (int side = 0; side < 2; side++) {
                        const int xx = side ? cx + r : cx - r;
                        if (xx < 0 || xx > G - 1) continue;
                        const int c = (zz * G + yy) * G + xx;
                        const int p0 = g_cellStart[c], p1 = g_cellStart[c + 1];
                        for (int p = p0; p < p1; p++) {
                            float4 T = g_sortedTgt[p];
                            float t2 = fmaf(T.x, T.x, fmaf(T.y, T.y, T.z * T.z));
                            float d  = fmaf(m2x, T.x, fmaf(m2y, T.y, fmaf(m2z, T.z, t2)));
                            ull pk = ((ull)map_f32(d) << 32) |
                                     (unsigned int)__float_as_int(T.w);
                            if (pk < best) { best = pk; bestD2 = d + s2; }
                        }
                    }
                    continue;
                }
                for (int xx = x0; xx <= x1; xx++) {
                    const int c = (zz * G + yy) * G + xx;
                    const int p0 = g_cellStart[c], p1 = g_cellStart[c + 1];
                    for (int p = p0; p < p1; p++) {
                        float4 T = g_sortedTgt[p];
                        float t2 = fmaf(T.x, T.x, fmaf(T.y, T.y, T.z * T.z));
                        float d  = fmaf(m2x, T.x, fmaf(m2y, T.y, fmaf(m2z, T.z, t2)));
                        ull pk = ((ull)map_f32(d) << 32) |
                                 (unsigned int)__float_as_int(T.w);
                        if (pk < best) { best = pk; bestD2 = d + s2; }
                    }
                }
            }
        }
    }

    const float dist = unmap_f32((unsigned int)(best >> 32)) + s2;
    const unsigned int idx = (unsigned int)(best & 0xFFFFFFFFu);
    if (i < out_size) out[i] = dist;
    if (n1 + i < out_size) out[n1 + i] = (float)idx;
}

// ---- launch ----------------------------------------------------------------

extern "C" void kernel_launch(void* const* d_in, const int* in_sizes, int n_in,
                              void* d_out, int out_size) {
    const float* src = (const float*)d_in[0];
    const float* tgt = (const float*)d_in[1];
    const int n1 = in_sizes[0] / 3;
    const int n2 = in_sizes[1] / 3;
    float* out = (float*)d_out;
    const int nmax = n1 > n2 ? n1 : n2;

    k_zero<<<(NCELLS + 255) / 256, 256>>>();
    k_count<<<(nmax + 255) / 256, 256>>>(src, tgt, n1, n2);
    k_scan1<<<NBLK, 1024>>>(0);
    k_scan1<<<NBLK, 1024>>>(1);
    k_scan2<<<1, 32>>>(0);
    k_scan2<<<1, 32>>>(1);
    k_scan3<<<(NCELLS + 255) / 256, 256>>>(n2);
    k_scatter<<<(nmax + 255) / 256, 256>>>(src, tgt, n1, n2);
    k_nn<<<(n1 + 127) / 128, 128>>>(src, out, n1, out_size);
}

// round 7
// speedup vs baseline: 3.3418x; 3.3418x over previous
#include <cuda_runtime.h>
#include <cuda_bf16.h>
#include <cstdint>

// ICPMatcher: exact NN via uniform grid + WARP-COOPERATIVE ring search.
//
// Targets counting-sorted into a 48^3 grid. One WARP per source: ring r's
// cells are strided over the 32 lanes (cube enum, interior skipped for r>=2),
// per-lane packed (monotone(d')|idx) u64 min, warp shfl-min per ring, then
// conservative prune ((r-1)h)^2 > bestD2 + margin. Scans a superset of the
// R6 cells -> argmin decisions bit-identical to all passing rounds.
// u64-min is order-independent -> scatter atomics can't change the result.

typedef unsigned long long ull;

#define N_MAX   16384
#define G       48
#define NCELLS  (G * G * G)          // 110592 = 108 * 1024
#define NBLK    (NCELLS / 1024)      // 108
#define BBOX    6.0f
#define CELLH   0.25f
#define INVH    4.0f

static __device__ int    g_histT[NCELLS];
static __device__ int    g_bsumT[NBLK];
static __device__ int    g_cellStart[NCELLS + 1];
static __device__ int    g_curT[NCELLS];
static __device__ float4 g_sortedTgt[N_MAX];   // (x,y,z, bitcast(origIdx))

static __device__ __forceinline__ unsigned int map_f32(float f) {
    unsigned int b = __float_as_uint(f);
    return (b & 0x80000000u) ? ~b : (b | 0x80000000u);
}
static __device__ __forceinline__ float unmap_f32(unsigned int m) {
    return __uint_as_float((m & 0x80000000u) ? (m ^ 0x80000000u) : ~m);
}
static __device__ __forceinline__ int clampi(int v, int lo, int hi) {
    return v < lo ? lo : (v > hi ? hi : v);
}
static __device__ __forceinline__ void cellOf(float x, float y, float z,
                                              int& cx, int& cy, int& cz) {
    cx = clampi((int)floorf((x + BBOX) * INVH), 0, G - 1);
    cy = clampi((int)floorf((y + BBOX) * INVH), 0, G - 1);
    cz = clampi((int)floorf((z + BBOX) * INVH), 0, G - 1);
}

// ---- preprocessing (5 launches; all globals device-side only) --------------

__global__ void k_zero() {
    int i = blockIdx.x * blockDim.x + threadIdx.x;
    if (i < NCELLS) g_histT[i] = 0;
}

__global__ void k_count(const float* __restrict__ tgt, int n2) {
    int i = blockIdx.x * blockDim.x + threadIdx.x;
    if (i < n2) {
        int cx, cy, cz;
        cellOf(tgt[3 * i], tgt[3 * i + 1], tgt[3 * i + 2], cx, cy, cz);
        atomicAdd(&g_histT[(cz * G + cy) * G + cx], 1);
    }
}

// Level-1 exclusive scan in place; block sums to g_bsumT.
__global__ __launch_bounds__(1024) void k_scan1() {
    __shared__ int sh[1024];
    const int t = threadIdx.x;
    const int g = blockIdx.x * 1024 + t;
    const int v = g_histT[g];
    sh[t] = v;
    __syncthreads();
#pragma unroll
    for (int off = 1; off < 1024; off <<= 1) {
        int add = (t >= off) ? sh[t - off] : 0;
        __syncthreads();
        sh[t] += add;
        __syncthreads();
    }
    g_histT[g] = sh[t] - v;
    if (t == 1023) g_bsumT[blockIdx.x] = sh[1023];
}

// Fuses block-sum prefix (serial <=107 adds per block, one 1024-cell chunk
// per 256-cell block) with the final cellStart materialization.
__global__ __launch_bounds__(256) void k_scan23(int n2) {
    __shared__ int base;
    if (threadIdx.x == 0) {
        int acc = 0;
        const int lim = blockIdx.x >> 2;     // chunk index of this block
        for (int k = 0; k < lim; k++) acc += g_bsumT[k];
        base = acc;
    }
    __syncthreads();
    const int g = blockIdx.x * 256 + threadIdx.x;
    const int v = g_histT[g] + base;
    g_cellStart[g] = v;
    g_curT[g] = v;
    if (g == 0) g_cellStart[NCELLS] = n2;
}

__global__ void k_scatter(const float* __restrict__ tgt, int n2) {
    int i = blockIdx.x * blockDim.x + threadIdx.x;
    if (i < n2) {
        float x = tgt[3 * i], y = tgt[3 * i + 1], z = tgt[3 * i + 2];
        int cx, cy, cz;
        cellOf(x, y, z, cx, cy, cz);
        int pos = atomicAdd(&g_curT[(cz * G + cy) * G + cx], 1);
        g_sortedTgt[pos] = make_float4(x, y, z, __int_as_float(i));
    }
}

// ---- warp-cooperative NN search --------------------------------------------

__global__ __launch_bounds__(256) void k_nn(const float* __restrict__ src,
                                            float* __restrict__ out,
                                            int n1, int out_size) {
    const int warp = (blockIdx.x * blockDim.x + threadIdx.x) >> 5;
    const int lane = threadIdx.x & 31;
    if (warp >= n1) return;
    const int i = warp;

    const float x = src[3 * i], y = src[3 * i + 1], z = src[3 * i + 2];
    const float m2x = -2.f * x, m2y = -2.f * y, m2z = -2.f * z;
    const float s2 = fmaf(x, x, fmaf(y, y, z * z));

    int cx, cy, cz;
    cellOf(x, y, z, cx, cy, cz);

    ull best = 0xFFFFFFFFFFFFFFFFull;
    float bestD2 = __int_as_float(0x7f800000);

    // r=1 scans the full 3x3x3 cube (rings 0+1); r>=2 scans shell only.
    for (int r = 1; r <= G; r++) {
        if (r > 1) {
            float lb = (float)(r - 1) * CELLH;
            if (lb * lb > bestD2 + 1e-3f) break;
        }
        const int side = 2 * r + 1;
        const int area = side * side;
        const int ncub = side * area;

        ull lbest = best;
        for (int t = lane; t < ncub; t += 32) {
            const int dz = t / area - r;
            const int rm = t % area;
            const int dy = rm / side - r;
            const int dx = rm % side - r;
            if (r > 1) {
                const int ch = max(abs(dx), max(abs(dy), abs(dz)));
                if (ch < r) continue;            // interior: already scanned
            }
            const int xx = cx + dx, yy = cy + dy, zz = cz + dz;
            if (xx < 0 || xx >= G || yy < 0 || yy >= G || zz < 0 || zz >= G)
                continue;
            const int c = (zz * G + yy) * G + xx;
            const int p0 = g_cellStart[c], p1 = g_cellStart[c + 1];
            for (int p = p0; p < p1; p++) {
                float4 T = g_sortedTgt[p];
                float t2 = fmaf(T.x, T.x, fmaf(T.y, T.y, T.z * T.z));
                float d  = fmaf(m2x, T.x, fmaf(m2y, T.y, fmaf(m2z, T.z, t2)));
                ull pk = ((ull)map_f32(d) << 32) |
                         (unsigned int)__float_as_int(T.w);
                if (pk < lbest) lbest = pk;
            }
        }

        // warp min-reduce of packed key
#pragma unroll
        for (int off = 16; off > 0; off >>= 1) {
            ull o = __shfl_xor_sync(0xFFFFFFFFu, lbest, off);
            if (o < lbest) lbest = o;
        }
        best = lbest;
        if (best != 0xFFFFFFFFFFFFFFFFull)
            bestD2 = unmap_f32((unsigned int)(best >> 32)) + s2;
    }

    if (lane == 0) {
        const float dist = unmap_f32((unsigned int)(best >> 32)) + s2;
        const unsigned int idx = (unsigned int)(best & 0xFFFFFFFFu);
        if (i < out_size) out[i] = dist;
        if (n1 + i < out_size) out[n1 + i] = (float)idx;
    }
}

// ---- launch ----------------------------------------------------------------

extern "C" void kernel_launch(void* const* d_in, const int* in_sizes, int n_in,
                              void* d_out, int out_size) {
    const float* src = (const float*)d_in[0];
    const float* tgt = (const float*)d_in[1];
    const int n1 = in_sizes[0] / 3;
    const int n2 = in_sizes[1] / 3;
    float* out = (float*)d_out;

    k_zero<<<(NCELLS + 255) / 256, 256>>>();
    k_count<<<(n2 + 255) / 256, 256>>>(tgt, n2);
    k_scan1<<<NBLK, 1024>>>();
    k_scan23<<<NCELLS / 256, 256>>>(n2);
    k_scatter<<<(n2 + 255) / 256, 256>>>(tgt, n2);

    const int warps_per_cta = 256 / 32;
    k_nn<<<(n1 + warps_per_cta - 1) / warps_per_cta, 256>>>(src, out, n1, out_size);
}

// round 8
// speedup vs baseline: 4.3115x; 1.2902x over previous
#include <cuda_runtime.h>
#include <cuda_bf16.h>
#include <cstdint>

// ICPMatcher: exact NN via uniform grid (32^3) + warp-cooperative ring search.
//
// Targets counting-sorted into a 32^3 grid (h=0.375). One WARP per source:
// ring r's cells strided over 32 lanes, per-lane packed (monotone(d')|idx)
// u64 min, warp shfl-min per ring, conservative prune
// ((r-1)h)^2 > bestD2 + margin. Scans a superset of cells containing the
// true NN -> argmin decisions bit-identical to all passing rounds.

typedef unsigned long long ull;

#define N_MAX   16384
#define G       32
#define NCELLS  (G * G * G)          // 32768 = 32 * 1024
#define NBLK    (NCELLS / 1024)      // 32
#define BBOX    6.0f
#define CELLH   0.375f
#define INVH    2.6666667f           // G / (2*BBOX)

static __device__ int    g_histT[NCELLS];
static __device__ int    g_bsumT[NBLK];
static __device__ int    g_cellStart[NCELLS + 1];
static __device__ int    g_curT[NCELLS];
static __device__ float4 g_sortedTgt[N_MAX];   // (x,y,z, bitcast(origIdx))

static __device__ __forceinline__ unsigned int map_f32(float f) {
    unsigned int b = __float_as_uint(f);
    return (b & 0x80000000u) ? ~b : (b | 0x80000000u);
}
static __device__ __forceinline__ float unmap_f32(unsigned int m) {
    return __uint_as_float((m & 0x80000000u) ? (m ^ 0x80000000u) : ~m);
}
static __device__ __forceinline__ int clampi(int v, int lo, int hi) {
    return v < lo ? lo : (v > hi ? hi : v);
}
static __device__ __forceinline__ void cellOf(float x, float y, float z,
                                              int& cx, int& cy, int& cz) {
    cx = clampi((int)floorf((x + BBOX) * INVH), 0, G - 1);
    cy = clampi((int)floorf((y + BBOX) * INVH), 0, G - 1);
    cz = clampi((int)floorf((z + BBOX) * INVH), 0, G - 1);
}

// ---- preprocessing ---------------------------------------------------------

__global__ void k_zero() {
    int i = blockIdx.x * blockDim.x + threadIdx.x;
    if (i < NCELLS / 4) ((int4*)g_histT)[i] = make_int4(0, 0, 0, 0);
}

__global__ void k_count(const float* __restrict__ tgt, int n2) {
    int i = blockIdx.x * blockDim.x + threadIdx.x;
    if (i < n2) {
        int cx, cy, cz;
        cellOf(tgt[3 * i], tgt[3 * i + 1], tgt[3 * i + 2], cx, cy, cz);
        atomicAdd(&g_histT[(cz * G + cy) * G + cx], 1);
    }
}

// Level-1 exclusive scan in place (warp-shfl based); block sums to g_bsumT.
__global__ __launch_bounds__(1024) void k_scan1() {
    __shared__ int wsum[32];
    const int t = threadIdx.x;
    const int lane = t & 31;
    const int wid = t >> 5;
    const int g = blockIdx.x * 1024 + t;
    const int v = g_histT[g];

    // inclusive warp scan
    int s = v;
#pragma unroll
    for (int off = 1; off < 32; off <<= 1) {
        int o = __shfl_up_sync(0xFFFFFFFFu, s, off);
        if (lane >= off) s += o;
    }
    if (lane == 31) wsum[wid] = s;
    __syncthreads();
    if (wid == 0) {
        int ws = (lane < 32) ? wsum[lane] : 0;
#pragma unroll
        for (int off = 1; off < 32; off <<= 1) {
            int o = __shfl_up_sync(0xFFFFFFFFu, ws, off);
            if (lane >= off) ws += o;
        }
        wsum[lane] = ws;
    }
    __syncthreads();
    const int incl = s + (wid > 0 ? wsum[wid - 1] : 0);
    g_histT[g] = incl - v;                   // exclusive within block
    if (t == 1023) g_bsumT[blockIdx.x] = incl;
}

// Block-sum prefix (<=31 serial adds, L2-hot) + cellStart materialization.
__global__ __launch_bounds__(256) void k_scan23(int n2) {
    __shared__ int base;
    if (threadIdx.x == 0) {
        int acc = 0;
        const int lim = blockIdx.x >> 2;     // 1024-cell chunk index
        for (int k = 0; k < lim; k++) acc += g_bsumT[k];
        base = acc;
    }
    __syncthreads();
    const int g = blockIdx.x * 256 + threadIdx.x;
    const int v = g_histT[g] + base;
    g_cellStart[g] = v;
    g_curT[g] = v;
    if (g == 0) g_cellStart[NCELLS] = n2;
}

__global__ void k_scatter(const float* __restrict__ tgt, int n2) {
    int i = blockIdx.x * blockDim.x + threadIdx.x;
    if (i < n2) {
        float x = tgt[3 * i], y = tgt[3 * i + 1], z = tgt[3 * i + 2];
        int cx, cy, cz;
        cellOf(x, y, z, cx, cy, cz);
        int pos = atomicAdd(&g_curT[(cz * G + cy) * G + cx], 1);
        g_sortedTgt[pos] = make_float4(x, y, z, __int_as_float(i));
    }
}

// ---- warp-cooperative NN search --------------------------------------------

__global__ __launch_bounds__(256) void k_nn(const float* __restrict__ src,
                                            float* __restrict__ out,
                                            int n1, int out_size) {
    const int warp = (blockIdx.x * blockDim.x + threadIdx.x) >> 5;
    const int lane = threadIdx.x & 31;
    if (warp >= n1) return;
    const int i = warp;

    const float x = src[3 * i], y = src[3 * i + 1], z = src[3 * i + 2];
    const float m2x = -2.f * x, m2y = -2.f * y, m2z = -2.f * z;
    const float s2 = fmaf(x, x, fmaf(y, y, z * z));

    int cx, cy, cz;
    cellOf(x, y, z, cx, cy, cz);

    ull best = 0xFFFFFFFFFFFFFFFFull;
    float bestD2 = __int_as_float(0x7f800000);

    // r=1 scans the full 3x3x3 cube (rings 0+1); r>=2 shell only.
    for (int r = 1; r <= G; r++) {
        if (r > 1) {
            float lb = (float)(r - 1) * CELLH;
            if (lb * lb > bestD2 + 1e-3f) break;
        }
        const int side = 2 * r + 1;
        const int area = side * side;
        const int ncub = side * area;

        ull lbest = best;
        for (int t = lane; t < ncub; t += 32) {
            const int dz = t / area - r;
            const int rm = t % area;
            const int dy = rm / side - r;
            const int dx = rm % side - r;
            if (r > 1) {
                const int ch = max(abs(dx), max(abs(dy), abs(dz)));
                if (ch < r) continue;            // interior already scanned
            }
            const int xx = cx + dx, yy = cy + dy, zz = cz + dz;
            if (xx < 0 || xx >= G || yy < 0 || yy >= G || zz < 0 || zz >= G)
                continue;
            const int c = (zz * G + yy) * G + xx;
            const int p0 = __ldg(&g_cellStart[c]);
            const int p1 = __ldg(&g_cellStart[c + 1]);
            for (int p = p0; p < p1; p++) {
                const float4 T = __ldg(&g_sortedTgt[p]);
                float t2 = fmaf(T.x, T.x, fmaf(T.y, T.y, T.z * T.z));
                float d  = fmaf(m2x, T.x, fmaf(m2y, T.y, fmaf(m2z, T.z, t2)));
                ull pk = ((ull)map_f32(d) << 32) |
                         (unsigned int)__float_as_int(T.w);
                if (pk < lbest) lbest = pk;
            }
        }

#pragma unroll
        for (int off = 16; off > 0; off >>= 1) {
            ull o = __shfl_xor_sync(0xFFFFFFFFu, lbest, off);
            if (o < lbest) lbest = o;
        }
        best = lbest;
        if (best != 0xFFFFFFFFFFFFFFFFull)
            bestD2 = unmap_f32((unsigned int)(best >> 32)) + s2;
    }

    if (lane == 0) {
        const float dist = unmap_f32((unsigned int)(best >> 32)) + s2;
        const unsigned int idx = (unsigned int)(best & 0xFFFFFFFFu);
        if (i < out_size) out[i] = dist;
        if (n1 + i < out_size) out[n1 + i] = (float)idx;
    }
}

// ---- launch ----------------------------------------------------------------

extern "C" void kernel_launch(void* const* d_in, const int* in_sizes, int n_in,
                              void* d_out, int out_size) {
    const float* src = (const float*)d_in[0];
    const float* tgt = (const float*)d_in[1];
    const int n1 = in_sizes[0] / 3;
    const int n2 = in_sizes[1] / 3;
    float* out = (float*)d_out;

    k_zero<<<(NCELLS / 4 + 255) / 256, 256>>>();
    k_count<<<(n2 + 255) / 256, 256>>>(tgt, n2);
    k_scan1<<<NBLK, 1024>>>();
    k_scan23<<<NCELLS / 256, 256>>>(n2);
    k_scatter<<<(n2 + 255) / 256, 256>>>(tgt, n2);

    const int warps_per_cta = 256 / 32;
    k_nn<<<(n1 + warps_per_cta - 1) / warps_per_cta, 256>>>(src, out, n1, out_size);
}